// round 1
// baseline (speedup 1.0000x reference)
#include <cuda_runtime.h>
#include <cstdint>

// Elastic warp: out(y,x,c) = sum_{a,b in 4x4} wy[a]*wx[b] * img[clamp(iy0+a-1), clamp(ix0+b-1), c]
// where (yy,xx) = (y,x) + bicubic-spline-upsampled 3x3 displacement*5.
//
// Strategy: one block = 32x32 output tile. Displacement field is extremely smooth
// (3x3 control points over 2048x4096), so the input footprint of a tile is
// ~ (32+4+eps)^2. We compute the exact footprint via a block-wide min/max of the
// integer tap bases, stage it into shared memory (conflict-free 12B-stride reads),
// and run the 4x4x3 gather entirely out of smem. Fallback to clamped global
// gathers if the footprint ever exceeds the smem budget (never for sane inputs).

#define HH 2048
#define WW 4096
#define W3 (WW * 3)

constexpr int TILE = 32;
constexpr int SMR  = 44;          // staged rows budget
constexpr int SMC  = 44;          // staged cols budget
constexpr int SMW  = SMC * 3;     // words per staged row (132)

__device__ __forceinline__ float cub_in(float t) {
    // (a+2)t^3 - (a+3)t^2 + 1, a = -0.5
    return ((1.5f * t - 2.5f) * t) * t + 1.0f;
}
__device__ __forceinline__ float cub_out(float t) {
    // a t^3 - 5a t^2 + 8a t - 4a, a = -0.5
    return ((-0.5f * t + 2.5f) * t - 4.0f) * t + 2.0f;
}

// Row of the (n_out x 3) spline-upsample matrix for coordinate u in [0,2].
__device__ __forceinline__ void spline_row(float u, float& b0, float& b1, float& b2) {
    float i0f = floorf(u);
    int   i0  = (int)i0f;
    float f   = u - i0f;
    float w0 = cub_out(f + 1.0f);
    float w1 = cub_in(f);
    float w2 = cub_in(1.0f - f);
    float w3 = cub_out(2.0f - f);
    if (i0 <= 0) {            // taps -1,0,1,2 -> clip to 0,0,1,2
        b0 = w0 + w1; b1 = w2; b2 = w3;
    } else if (i0 == 1) {     // taps 0,1,2,3 -> 0,1,2,2
        b0 = w0; b1 = w1; b2 = w2 + w3;
    } else {                  // i0 >= 2: taps 1,2,3,4 -> 1,2,2,2
        b0 = w1 * 0.0f + w0;  // b0 unused slot: taps start at 1
        b0 = 0.0f; b1 = w0; b2 = w1 + w2 + w3;
    }
}

__global__ void __launch_bounds__(256, 2)
elastic_warp_kernel(const float* __restrict__ img,
                    const float* __restrict__ disp,
                    float* __restrict__ out)
{
    __shared__ float sD[18];
    __shared__ float sTile[SMR * SMW];
    __shared__ int   sRed[8][4];

    const int tid  = threadIdx.x;
    const int lane = tid & 31;
    const int wid  = tid >> 5;

    if (tid < 18) sD[tid] = disp[tid] * 5.0f;
    __syncthreads();

    const int px  = blockIdx.x * TILE + lane;   // column (fixed per thread)
    const int py0 = blockIdx.y * TILE + wid;    // rows py0 + 8k, k=0..3

    // Bx row for this column
    float bx0, bx1, bx2;
    spline_row((float)px * (2.0f / (WW - 1)), bx0, bx1, bx2);

    // g[d][y] = sum_x D[d,y,x]*Bx[x]
    float g[2][3];
#pragma unroll
    for (int d = 0; d < 2; ++d)
#pragma unroll
        for (int y = 0; y < 3; ++y)
            g[d][y] = sD[d * 9 + y * 3 + 0] * bx0 +
                      sD[d * 9 + y * 3 + 1] * bx1 +
                      sD[d * 9 + y * 3 + 2] * bx2;

    float yyv[4], xxv[4];
    int minIy =  0x7fffffff, maxIy = -0x7fffffff;
    int minIx =  0x7fffffff, maxIx = -0x7fffffff;
#pragma unroll
    for (int k = 0; k < 4; ++k) {
        int py = py0 + 8 * k;
        float by0, by1, by2;
        spline_row((float)py * (2.0f / (HH - 1)), by0, by1, by2);
        float d0 = by0 * g[0][0] + by1 * g[0][1] + by2 * g[0][2];
        float d1 = by0 * g[1][0] + by1 * g[1][1] + by2 * g[1][2];
        float yy = (float)py + d0;
        float xx = (float)px + d1;
        yyv[k] = yy; xxv[k] = xx;
        int iy = (int)floorf(yy), ix = (int)floorf(xx);
        minIy = min(minIy, iy); maxIy = max(maxIy, iy);
        minIx = min(minIx, ix); maxIx = max(maxIx, ix);
    }

    // warp reduce
#pragma unroll
    for (int o = 16; o > 0; o >>= 1) {
        minIy = min(minIy, __shfl_xor_sync(0xffffffffu, minIy, o));
        maxIy = max(maxIy, __shfl_xor_sync(0xffffffffu, maxIy, o));
        minIx = min(minIx, __shfl_xor_sync(0xffffffffu, minIx, o));
        maxIx = max(maxIx, __shfl_xor_sync(0xffffffffu, maxIx, o));
    }
    if (lane == 0) {
        sRed[wid][0] = minIy; sRed[wid][1] = maxIy;
        sRed[wid][2] = minIx; sRed[wid][3] = maxIx;
    }
    __syncthreads();
#pragma unroll
    for (int w = 0; w < 8; ++w) {
        minIy = min(minIy, sRed[w][0]); maxIy = max(maxIy, sRed[w][1]);
        minIx = min(minIx, sRed[w][2]); maxIx = max(maxIx, sRed[w][3]);
    }

    const int r0 = minIy - 1, r1 = maxIy + 2;
    const int c0 = minIx - 1, c1 = maxIx + 2;
    const int nr = r1 - r0 + 1;
    const int nc = c1 - c0 + 1;
    const bool staged = (nr <= SMR) && (nc <= SMC);

    if (staged) {
        const int ncw = nc * 3;
        const bool interior = (r0 >= 0) && (r1 < HH) && (c0 >= 0) && (c1 < WW);
        if (interior) {
            const float* src0 = img + (size_t)r0 * W3 + (size_t)c0 * 3;
            for (int r = wid; r < nr; r += 8) {
                const float* s = src0 + (size_t)r * W3;
                float* dsts = sTile + r * SMW;
                for (int cw = lane; cw < ncw; cw += 32)
                    dsts[cw] = s[cw];
            }
        } else {
            for (int r = wid; r < nr; r += 8) {
                int rr = min(max(r0 + r, 0), HH - 1);
                const float* s = img + (size_t)rr * W3;
                float* dsts = sTile + r * SMW;
                for (int cw = lane; cw < ncw; cw += 32) {
                    int c3 = cw / 3;
                    int ch = cw - 3 * c3;
                    int cc = min(max(c0 + c3, 0), WW - 1);
                    dsts[cw] = s[cc * 3 + ch];
                }
            }
        }
    }
    __syncthreads();

#pragma unroll
    for (int k = 0; k < 4; ++k) {
        const int py = py0 + 8 * k;
        const float yy = yyv[k], xx = xxv[k];
        const float iyf = floorf(yy), ixf = floorf(xx);
        const float fy = yy - iyf, fx = xx - ixf;
        const int iy = (int)iyf, ix = (int)ixf;

        const float wy0 = cub_out(fy + 1.0f);
        const float wy1 = cub_in(fy);
        const float wy2 = cub_in(1.0f - fy);
        const float wy3 = cub_out(2.0f - fy);
        const float wx0 = cub_out(fx + 1.0f);
        const float wx1 = cub_in(fx);
        const float wx2 = cub_in(1.0f - fx);
        const float wx3 = cub_out(2.0f - fx);
        const float wy[4] = {wy0, wy1, wy2, wy3};
        const float wxa[4] = {wx0, wx1, wx2, wx3};

        float a0 = 0.0f, a1 = 0.0f, a2 = 0.0f;
        if (staged) {
            const float* base = sTile + (iy - 1 - r0) * SMW + (ix - 1 - c0) * 3;
#pragma unroll
            for (int a = 0; a < 4; ++a) {
                const float* p = base + a * SMW;
                float rc0 = wx0 * p[0] + wx1 * p[3] + wx2 * p[6] + wx3 * p[9];
                float rc1 = wx0 * p[1] + wx1 * p[4] + wx2 * p[7] + wx3 * p[10];
                float rc2 = wx0 * p[2] + wx1 * p[5] + wx2 * p[8] + wx3 * p[11];
                a0 += wy[a] * rc0;
                a1 += wy[a] * rc1;
                a2 += wy[a] * rc2;
            }
        } else {
            // clamped global-gather fallback (footprint exceeded smem budget)
#pragma unroll
            for (int a = 0; a < 4; ++a) {
                int ty = min(max(iy - 1 + a, 0), HH - 1);
                const float* rowp = img + (size_t)ty * W3;
                float rc0 = 0.0f, rc1 = 0.0f, rc2 = 0.0f;
#pragma unroll
                for (int b = 0; b < 4; ++b) {
                    int txc = min(max(ix - 1 + b, 0), WW - 1);
                    const float* p = rowp + txc * 3;
                    rc0 += wxa[b] * p[0];
                    rc1 += wxa[b] * p[1];
                    rc2 += wxa[b] * p[2];
                }
                a0 += wy[a] * rc0;
                a1 += wy[a] * rc1;
                a2 += wy[a] * rc2;
            }
        }

        float* o = out + ((size_t)py * WW + px) * 3;
        o[0] = a0; o[1] = a1; o[2] = a2;
    }
}

extern "C" void kernel_launch(void* const* d_in, const int* in_sizes, int n_in,
                              void* d_out, int out_size) {
    const float* img  = (const float*)d_in[0];   // (2048, 4096, 3) f32
    const float* disp = (const float*)d_in[1];   // (2, 3, 3) f32
    float* out = (float*)d_out;                  // (2048, 4096, 3) f32

    dim3 grid(WW / TILE, HH / TILE);
    elastic_warp_kernel<<<grid, 256>>>(img, disp, out);
}

// round 4
// speedup vs baseline: 1.5453x; 1.5453x over previous
#include <cuda_runtime.h>
#include <cstdint>

// Elastic warp, R4 (re-bench of R2/R3 candidate after two broker infra failures;
// source audited: 31.2KB static smem, all smem indices in-bounds, single
// graph-capturable launch, no allocations).
// RGBA float4 smem staging + LDS.128 gathers.
// out(y,x,c) = sum_{4x4 taps} wy*wx * img[clamp(iy0+a), clamp(ix0+b), c]
// Displacement field = bicubic upsample of 3x3 control points * 5 (very smooth),
// so a 32x32 output tile's input footprint fits in ~40x40; computed exactly via
// block-wide min/max with a global-gather fallback if it ever exceeds budget.

#define HH 2048
#define WW 4096
#define W3 (WW * 3)

constexpr int TILE = 32;
constexpr int SMR  = 44;          // staged rows budget
constexpr int SMC  = 44;          // staged cols budget (float4 each)

__device__ __forceinline__ float cub_in(float t) {
    // (a+2)t^3 - (a+3)t^2 + 1, a = -0.5
    return ((1.5f * t - 2.5f) * t) * t + 1.0f;
}
__device__ __forceinline__ float cub_out(float t) {
    // a t^3 - 5a t^2 + 8a t - 4a, a = -0.5
    return ((-0.5f * t + 2.5f) * t - 4.0f) * t + 2.0f;
}

// Row of the (n_out x 3) spline-upsample matrix for coordinate u in [0,2].
__device__ __forceinline__ void spline_row(float u, float& b0, float& b1, float& b2) {
    float i0f = floorf(u);
    int   i0  = (int)i0f;
    float f   = u - i0f;
    float w0 = cub_out(f + 1.0f);
    float w1 = cub_in(f);
    float w2 = cub_in(1.0f - f);
    float w3 = cub_out(2.0f - f);
    if (i0 <= 0) {            // taps -1,0,1,2 -> clip 0,0,1,2
        b0 = w0 + w1; b1 = w2; b2 = w3;
    } else if (i0 == 1) {     // taps 0,1,2,3 -> 0,1,2,2
        b0 = w0; b1 = w1; b2 = w2 + w3;
    } else {                  // taps 1,2,3,4 -> 1,2,2,2
        b0 = 0.0f; b1 = w0; b2 = w1 + w2 + w3;
    }
}

// Compute sample coords for (py, px) given control-point row dot products g.
__device__ __forceinline__ void sample_coords(int py, int px,
                                              const float g[2][3],
                                              float& yy, float& xx) {
    float by0, by1, by2;
    spline_row((float)py * (2.0f / (HH - 1)), by0, by1, by2);
    yy = (float)py + by0 * g[0][0] + by1 * g[0][1] + by2 * g[0][2];
    xx = (float)px + by0 * g[1][0] + by1 * g[1][1] + by2 * g[1][2];
}

__global__ void __launch_bounds__(256, 3)
elastic_warp_kernel(const float* __restrict__ img,
                    const float* __restrict__ disp,
                    float* __restrict__ out)
{
    __shared__ float  sD[18];
    __shared__ float4 sTile[SMR * SMC];
    __shared__ int    sRed[8][4];

    const int tid  = threadIdx.x;
    const int lane = tid & 31;
    const int wid  = tid >> 5;

    if (tid < 18) sD[tid] = disp[tid] * 5.0f;
    __syncthreads();

    const int px  = blockIdx.x * TILE + lane;   // column (fixed per thread)
    const int py0 = blockIdx.y * TILE + wid;    // rows py0 + 8k, k=0..3

    // Bx row for this column
    float bx0, bx1, bx2;
    spline_row((float)px * (2.0f / (WW - 1)), bx0, bx1, bx2);

    // g[d][y] = sum_x D[d,y,x]*Bx[x]  (per-thread, reused in both phases)
    float g[2][3];
#pragma unroll
    for (int d = 0; d < 2; ++d)
#pragma unroll
        for (int y = 0; y < 3; ++y)
            g[d][y] = sD[d * 9 + y * 3 + 0] * bx0 +
                      sD[d * 9 + y * 3 + 1] * bx1 +
                      sD[d * 9 + y * 3 + 2] * bx2;

    // Phase 1: exact footprint (block min/max of tap bases)
    int minIy =  0x7fffffff, maxIy = -0x7fffffff;
    int minIx =  0x7fffffff, maxIx = -0x7fffffff;
#pragma unroll
    for (int k = 0; k < 4; ++k) {
        float yy, xx;
        sample_coords(py0 + 8 * k, px, g, yy, xx);
        int iy = (int)floorf(yy), ix = (int)floorf(xx);
        minIy = min(minIy, iy); maxIy = max(maxIy, iy);
        minIx = min(minIx, ix); maxIx = max(maxIx, ix);
    }
#pragma unroll
    for (int o = 16; o > 0; o >>= 1) {
        minIy = min(minIy, __shfl_xor_sync(0xffffffffu, minIy, o));
        maxIy = max(maxIy, __shfl_xor_sync(0xffffffffu, maxIy, o));
        minIx = min(minIx, __shfl_xor_sync(0xffffffffu, minIx, o));
        maxIx = max(maxIx, __shfl_xor_sync(0xffffffffu, maxIx, o));
    }
    if (lane == 0) {
        sRed[wid][0] = minIy; sRed[wid][1] = maxIy;
        sRed[wid][2] = minIx; sRed[wid][3] = maxIx;
    }
    __syncthreads();
#pragma unroll
    for (int w = 0; w < 8; ++w) {
        minIy = min(minIy, sRed[w][0]); maxIy = max(maxIy, sRed[w][1]);
        minIx = min(minIx, sRed[w][2]); maxIx = max(maxIx, sRed[w][3]);
    }

    const int r0 = minIy - 1, r1 = maxIy + 2;
    const int c0 = minIx - 1, c1 = maxIx + 2;
    const int nr = r1 - r0 + 1;
    const int nc = c1 - c0 + 1;
    const bool staged = (nr <= SMR) && (nc <= SMC);

    // Phase 2: stage footprint as RGBA float4 (conflict-free LDS.128 gathers)
    if (staged) {
        const bool interior = (r0 >= 0) && (r1 < HH) && (c0 >= 0) && (c1 < WW);
        if (interior) {
            const float* src0 = img + (size_t)r0 * W3 + (size_t)c0 * 3;
            for (int r = wid; r < nr; r += 8) {
                const float* s = src0 + (size_t)r * W3;
                float4* dsts = sTile + r * SMC;
                for (int c = lane; c < nc; c += 32) {
                    const float* p = s + c * 3;
                    dsts[c] = make_float4(p[0], p[1], p[2], 0.0f);
                }
            }
        } else {
            for (int r = wid; r < nr; r += 8) {
                int rr = min(max(r0 + r, 0), HH - 1);
                const float* s = img + (size_t)rr * W3;
                float4* dsts = sTile + r * SMC;
                for (int c = lane; c < nc; c += 32) {
                    int cc = min(max(c0 + c, 0), WW - 1);
                    const float* p = s + cc * 3;
                    dsts[c] = make_float4(p[0], p[1], p[2], 0.0f);
                }
            }
        }
    }
    __syncthreads();

    // Phase 3: 4x4 cubic gather per output pixel
#pragma unroll
    for (int k = 0; k < 4; ++k) {
        const int py = py0 + 8 * k;
        float yy, xx;
        sample_coords(py, px, g, yy, xx);
        const float iyf = floorf(yy), ixf = floorf(xx);
        const float fy = yy - iyf, fx = xx - ixf;
        const int iy = (int)iyf, ix = (int)ixf;

        const float wy[4] = { cub_out(fy + 1.0f), cub_in(fy),
                              cub_in(1.0f - fy), cub_out(2.0f - fy) };
        const float wx0 = cub_out(fx + 1.0f);
        const float wx1 = cub_in(fx);
        const float wx2 = cub_in(1.0f - fx);
        const float wx3 = cub_out(2.0f - fx);

        float a0 = 0.0f, a1 = 0.0f, a2 = 0.0f;
        if (staged) {
            const float4* p = sTile + (iy - 1 - r0) * SMC + (ix - 1 - c0);
#pragma unroll
            for (int a = 0; a < 4; ++a) {
                float4 t0 = p[0], t1 = p[1], t2 = p[2], t3 = p[3];
                p += SMC;
                float rc0 = fmaf(wx0, t0.x, fmaf(wx1, t1.x, fmaf(wx2, t2.x, wx3 * t3.x)));
                float rc1 = fmaf(wx0, t0.y, fmaf(wx1, t1.y, fmaf(wx2, t2.y, wx3 * t3.y)));
                float rc2 = fmaf(wx0, t0.z, fmaf(wx1, t1.z, fmaf(wx2, t2.z, wx3 * t3.z)));
                a0 = fmaf(wy[a], rc0, a0);
                a1 = fmaf(wy[a], rc1, a1);
                a2 = fmaf(wy[a], rc2, a2);
            }
        } else {
            // clamped global-gather fallback (footprint exceeded smem budget)
            const float wxa[4] = {wx0, wx1, wx2, wx3};
#pragma unroll
            for (int a = 0; a < 4; ++a) {
                int ty = min(max(iy - 1 + a, 0), HH - 1);
                const float* rowp = img + (size_t)ty * W3;
                float rc0 = 0.0f, rc1 = 0.0f, rc2 = 0.0f;
#pragma unroll
                for (int b = 0; b < 4; ++b) {
                    int txc = min(max(ix - 1 + b, 0), WW - 1);
                    const float* p = rowp + txc * 3;
                    rc0 = fmaf(wxa[b], p[0], rc0);
                    rc1 = fmaf(wxa[b], p[1], rc1);
                    rc2 = fmaf(wxa[b], p[2], rc2);
                }
                a0 = fmaf(wy[a], rc0, a0);
                a1 = fmaf(wy[a], rc1, a1);
                a2 = fmaf(wy[a], rc2, a2);
            }
        }

        float* o = out + ((size_t)py * WW + px) * 3;
        o[0] = a0; o[1] = a1; o[2] = a2;
    }
}

extern "C" void kernel_launch(void* const* d_in, const int* in_sizes, int n_in,
                              void* d_out, int out_size) {
    const float* img  = (const float*)d_in[0];   // (2048, 4096, 3) f32
    const float* disp = (const float*)d_in[1];   // (2, 3, 3) f32
    float* out = (float*)d_out;                  // (2048, 4096, 3) f32

    dim3 grid(WW / TILE, HH / TILE);
    elastic_warp_kernel<<<grid, 256>>>(img, disp, out);
}

// round 5
// speedup vs baseline: 1.6236x; 1.0507x over previous
#include <cuda_runtime.h>
#include <cstdint>

// Elastic warp, R5: R4 + (a) coords computed once and cached in regs,
// (b) disp read via uniform broadcast loads (no smem stage / one fewer barrier),
// (c) cvt.rd-based floors.
// out(y,x,c) = sum_{4x4 taps} wy*wx * img[clamp(iy0+a), clamp(ix0+b), c]

#define HH 2048
#define WW 4096
#define W3 (WW * 3)

constexpr int TILE = 32;
constexpr int SMR  = 44;          // staged rows budget
constexpr int SMC  = 44;          // staged cols budget (float4 each)

__device__ __forceinline__ float cub_in(float t) {
    // (a+2)t^3 - (a+3)t^2 + 1, a = -0.5
    return ((1.5f * t - 2.5f) * t) * t + 1.0f;
}
__device__ __forceinline__ float cub_out(float t) {
    // a t^3 - 5a t^2 + 8a t - 4a, a = -0.5
    return ((-0.5f * t + 2.5f) * t - 4.0f) * t + 2.0f;
}

// Row of the (n_out x 3) spline-upsample matrix for coordinate u in [0,2].
__device__ __forceinline__ void spline_row(float u, float& b0, float& b1, float& b2) {
    int   i0 = __float2int_rd(u);
    float f  = u - (float)i0;
    float w0 = cub_out(f + 1.0f);
    float w1 = cub_in(f);
    float w2 = cub_in(1.0f - f);
    float w3 = cub_out(2.0f - f);
    if (i0 <= 0) {            // taps -1,0,1,2 -> clip 0,0,1,2
        b0 = w0 + w1; b1 = w2; b2 = w3;
    } else if (i0 == 1) {     // taps 0,1,2,3 -> 0,1,2,2
        b0 = w0; b1 = w1; b2 = w2 + w3;
    } else {                  // taps 1,2,3,4 -> 1,2,2,2
        b0 = 0.0f; b1 = w0; b2 = w1 + w2 + w3;
    }
}

__global__ void __launch_bounds__(256, 3)
elastic_warp_kernel(const float* __restrict__ img,
                    const float* __restrict__ disp,
                    float* __restrict__ out)
{
    __shared__ float4 sTile[SMR * SMC];
    __shared__ int    sRed[8][4];

    const int tid  = threadIdx.x;
    const int lane = tid & 31;
    const int wid  = tid >> 5;

    const int px  = blockIdx.x * TILE + lane;   // column (fixed per thread)
    const int py0 = blockIdx.y * TILE + wid;    // rows py0 + 8k, k=0..3

    // Bx row for this column
    float bx0, bx1, bx2;
    spline_row((float)px * (2.0f / (WW - 1)), bx0, bx1, bx2);

    // g[d][y] = sum_x 5*D[d,y,x]*Bx[x]; disp read as uniform broadcast loads
    float g[2][3];
#pragma unroll
    for (int d = 0; d < 2; ++d)
#pragma unroll
        for (int y = 0; y < 3; ++y) {
            const float* dp = disp + d * 9 + y * 3;
            g[d][y] = 5.0f * (dp[0] * bx0 + dp[1] * bx1 + dp[2] * bx2);
        }

    // Phase 1: coords (cached) + exact footprint via block min/max of tap bases
    float yyv[4], xxv[4];
    int minIy =  0x7fffffff, maxIy = -0x7fffffff;
    int minIx =  0x7fffffff, maxIx = -0x7fffffff;
#pragma unroll
    for (int k = 0; k < 4; ++k) {
        int py = py0 + 8 * k;
        float by0, by1, by2;
        spline_row((float)py * (2.0f / (HH - 1)), by0, by1, by2);
        float yy = (float)py + by0 * g[0][0] + by1 * g[0][1] + by2 * g[0][2];
        float xx = (float)px + by0 * g[1][0] + by1 * g[1][1] + by2 * g[1][2];
        yyv[k] = yy; xxv[k] = xx;
        int iy = __float2int_rd(yy), ix = __float2int_rd(xx);
        minIy = min(minIy, iy); maxIy = max(maxIy, iy);
        minIx = min(minIx, ix); maxIx = max(maxIx, ix);
    }
#pragma unroll
    for (int o = 16; o > 0; o >>= 1) {
        minIy = min(minIy, __shfl_xor_sync(0xffffffffu, minIy, o));
        maxIy = max(maxIy, __shfl_xor_sync(0xffffffffu, maxIy, o));
        minIx = min(minIx, __shfl_xor_sync(0xffffffffu, minIx, o));
        maxIx = max(maxIx, __shfl_xor_sync(0xffffffffu, maxIx, o));
    }
    if (lane == 0) {
        sRed[wid][0] = minIy; sRed[wid][1] = maxIy;
        sRed[wid][2] = minIx; sRed[wid][3] = maxIx;
    }
    __syncthreads();
#pragma unroll
    for (int w = 0; w < 8; ++w) {
        minIy = min(minIy, sRed[w][0]); maxIy = max(maxIy, sRed[w][1]);
        minIx = min(minIx, sRed[w][2]); maxIx = max(maxIx, sRed[w][3]);
    }

    const int r0 = minIy - 1, r1 = maxIy + 2;
    const int c0 = minIx - 1, c1 = maxIx + 2;
    const int nr = r1 - r0 + 1;
    const int nc = c1 - c0 + 1;
    const bool staged = (nr <= SMR) && (nc <= SMC);

    // Phase 2: stage footprint as RGBA float4 (conflict-free LDS.128 gathers)
    if (staged) {
        const bool interior = (r0 >= 0) && (r1 < HH) && (c0 >= 0) && (c1 < WW);
        if (interior) {
            const float* src0 = img + (size_t)r0 * W3 + (size_t)c0 * 3;
            for (int r = wid; r < nr; r += 8) {
                const float* s = src0 + (size_t)r * W3;
                float4* dsts = sTile + r * SMC;
                for (int c = lane; c < nc; c += 32) {
                    const float* p = s + c * 3;
                    dsts[c] = make_float4(p[0], p[1], p[2], 0.0f);
                }
            }
        } else {
            for (int r = wid; r < nr; r += 8) {
                int rr = min(max(r0 + r, 0), HH - 1);
                const float* s = img + (size_t)rr * W3;
                float4* dsts = sTile + r * SMC;
                for (int c = lane; c < nc; c += 32) {
                    int cc = min(max(c0 + c, 0), WW - 1);
                    const float* p = s + cc * 3;
                    dsts[c] = make_float4(p[0], p[1], p[2], 0.0f);
                }
            }
        }
    }
    __syncthreads();

    // Phase 3: 4x4 cubic gather per output pixel (coords from cache)
#pragma unroll
    for (int k = 0; k < 4; ++k) {
        const int py = py0 + 8 * k;
        const float yy = yyv[k], xx = xxv[k];
        const int iy = __float2int_rd(yy), ix = __float2int_rd(xx);
        const float fy = yy - (float)iy;
        const float fx = xx - (float)ix;

        const float wy[4] = { cub_out(fy + 1.0f), cub_in(fy),
                              cub_in(1.0f - fy), cub_out(2.0f - fy) };
        const float wx0 = cub_out(fx + 1.0f);
        const float wx1 = cub_in(fx);
        const float wx2 = cub_in(1.0f - fx);
        const float wx3 = cub_out(2.0f - fx);

        float a0 = 0.0f, a1 = 0.0f, a2 = 0.0f;
        if (staged) {
            const float4* p = sTile + (iy - 1 - r0) * SMC + (ix - 1 - c0);
#pragma unroll
            for (int a = 0; a < 4; ++a) {
                float4 t0 = p[0], t1 = p[1], t2 = p[2], t3 = p[3];
                p += SMC;
                float rc0 = fmaf(wx0, t0.x, fmaf(wx1, t1.x, fmaf(wx2, t2.x, wx3 * t3.x)));
                float rc1 = fmaf(wx0, t0.y, fmaf(wx1, t1.y, fmaf(wx2, t2.y, wx3 * t3.y)));
                float rc2 = fmaf(wx0, t0.z, fmaf(wx1, t1.z, fmaf(wx2, t2.z, wx3 * t3.z)));
                a0 = fmaf(wy[a], rc0, a0);
                a1 = fmaf(wy[a], rc1, a1);
                a2 = fmaf(wy[a], rc2, a2);
            }
        } else {
            // clamped global-gather fallback (footprint exceeded smem budget)
            const float wxa[4] = {wx0, wx1, wx2, wx3};
#pragma unroll
            for (int a = 0; a < 4; ++a) {
                int ty = min(max(iy - 1 + a, 0), HH - 1);
                const float* rowp = img + (size_t)ty * W3;
                float rc0 = 0.0f, rc1 = 0.0f, rc2 = 0.0f;
#pragma unroll
                for (int b = 0; b < 4; ++b) {
                    int txc = min(max(ix - 1 + b, 0), WW - 1);
                    const float* p = rowp + txc * 3;
                    rc0 = fmaf(wxa[b], p[0], rc0);
                    rc1 = fmaf(wxa[b], p[1], rc1);
                    rc2 = fmaf(wxa[b], p[2], rc2);
                }
                a0 = fmaf(wy[a], rc0, a0);
                a1 = fmaf(wy[a], rc1, a1);
                a2 = fmaf(wy[a], rc2, a2);
            }
        }

        float* o = out + ((size_t)py * WW + px) * 3;
        o[0] = a0; o[1] = a1; o[2] = a2;
    }
}

extern "C" void kernel_launch(void* const* d_in, const int* in_sizes, int n_in,
                              void* d_out, int out_size) {
    const float* img  = (const float*)d_in[0];   // (2048, 4096, 3) f32
    const float* disp = (const float*)d_in[1];   // (2, 3, 3) f32
    float* out = (float*)d_out;                  // (2048, 4096, 3) f32

    dim3 grid(WW / TILE, HH / TILE);
    elastic_warp_kernel<<<grid, 256>>>(img, disp, out);
}

// round 7
// speedup vs baseline: 1.9009x; 1.1708x over previous
#include <cuda_runtime.h>
#include <cuda_fp16.h>
#include <cstdint>

// Elastic warp, R7 (= R6 re-bench after broker infra failure; source audited:
// 15.6KB static smem, same launch config as passing R5, single graph-capturable
// launch, no allocations).
// fp16 texel staging (half4 RG|B0, 8B/texel): gather taps become LDS.64
// (2 crossbar phases) instead of LDS.128 (4), halving the shared-memory
// crossbar cost that R5's profile showed binding (L1 59% @ issue 42%).
// Accumulation remains fp32; taps are RN-rounded fp16.

#define HH 2048
#define WW 4096
#define W3 (WW * 3)

constexpr int TILE = 32;
constexpr int SMR  = 44;          // staged rows budget
constexpr int SMC  = 44;          // staged cols budget (half4 each)

__device__ __forceinline__ float cub_in(float t) {
    // (a+2)t^3 - (a+3)t^2 + 1, a = -0.5
    return ((1.5f * t - 2.5f) * t) * t + 1.0f;
}
__device__ __forceinline__ float cub_out(float t) {
    // a t^3 - 5a t^2 + 8a t - 4a, a = -0.5
    return ((-0.5f * t + 2.5f) * t - 4.0f) * t + 2.0f;
}

// Row of the (n_out x 3) spline-upsample matrix for coordinate u in [0,2].
__device__ __forceinline__ void spline_row(float u, float& b0, float& b1, float& b2) {
    int   i0 = __float2int_rd(u);
    float f  = u - (float)i0;
    float w0 = cub_out(f + 1.0f);
    float w1 = cub_in(f);
    float w2 = cub_in(1.0f - f);
    float w3 = cub_out(2.0f - f);
    if (i0 <= 0) {            // taps -1,0,1,2 -> clip 0,0,1,2
        b0 = w0 + w1; b1 = w2; b2 = w3;
    } else if (i0 == 1) {     // taps 0,1,2,3 -> 0,1,2,2
        b0 = w0; b1 = w1; b2 = w2 + w3;
    } else {                  // taps 1,2,3,4 -> 1,2,2,2
        b0 = 0.0f; b1 = w0; b2 = w1 + w2 + w3;
    }
}

__device__ __forceinline__ uint2 pack_texel(float r, float g, float b) {
    __half2 rg = __floats2half2_rn(r, g);
    __half2 bz = __floats2half2_rn(b, 0.0f);
    uint2 v;
    v.x = *reinterpret_cast<uint32_t*>(&rg);
    v.y = *reinterpret_cast<uint32_t*>(&bz);
    return v;
}

__device__ __forceinline__ void unpack_texel(uint2 v, float& r, float& g, float& b) {
    __half2 rg = *reinterpret_cast<__half2*>(&v.x);
    __half2 bz = *reinterpret_cast<__half2*>(&v.y);
    float2 f0 = __half22float2(rg);
    r = f0.x; g = f0.y;
    b = __low2float(bz);
}

__global__ void __launch_bounds__(256, 3)
elastic_warp_kernel(const float* __restrict__ img,
                    const float* __restrict__ disp,
                    float* __restrict__ out)
{
    __shared__ uint2 sTile[SMR * SMC];     // half4 texels, 15.5 KB
    __shared__ int   sRed[8][4];

    const int tid  = threadIdx.x;
    const int lane = tid & 31;
    const int wid  = tid >> 5;

    const int px  = blockIdx.x * TILE + lane;   // column (fixed per thread)
    const int py0 = blockIdx.y * TILE + wid;    // rows py0 + 8k, k=0..3

    // Bx row for this column
    float bx0, bx1, bx2;
    spline_row((float)px * (2.0f / (WW - 1)), bx0, bx1, bx2);

    // g[d][y] = sum_x 5*D[d,y,x]*Bx[x]; disp read as uniform broadcast loads
    float g[2][3];
#pragma unroll
    for (int d = 0; d < 2; ++d)
#pragma unroll
        for (int y = 0; y < 3; ++y) {
            const float* dp = disp + d * 9 + y * 3;
            g[d][y] = 5.0f * (dp[0] * bx0 + dp[1] * bx1 + dp[2] * bx2);
        }

    // Phase 1: coords (cached) + exact footprint via block min/max of tap bases
    float yyv[4], xxv[4];
    int minIy =  0x7fffffff, maxIy = -0x7fffffff;
    int minIx =  0x7fffffff, maxIx = -0x7fffffff;
#pragma unroll
    for (int k = 0; k < 4; ++k) {
        int py = py0 + 8 * k;
        float by0, by1, by2;
        spline_row((float)py * (2.0f / (HH - 1)), by0, by1, by2);
        float yy = (float)py + by0 * g[0][0] + by1 * g[0][1] + by2 * g[0][2];
        float xx = (float)px + by0 * g[1][0] + by1 * g[1][1] + by2 * g[1][2];
        yyv[k] = yy; xxv[k] = xx;
        int iy = __float2int_rd(yy), ix = __float2int_rd(xx);
        minIy = min(minIy, iy); maxIy = max(maxIy, iy);
        minIx = min(minIx, ix); maxIx = max(maxIx, ix);
    }
#pragma unroll
    for (int o = 16; o > 0; o >>= 1) {
        minIy = min(minIy, __shfl_xor_sync(0xffffffffu, minIy, o));
        maxIy = max(maxIy, __shfl_xor_sync(0xffffffffu, maxIy, o));
        minIx = min(minIx, __shfl_xor_sync(0xffffffffu, minIx, o));
        maxIx = max(maxIx, __shfl_xor_sync(0xffffffffu, maxIx, o));
    }
    if (lane == 0) {
        sRed[wid][0] = minIy; sRed[wid][1] = maxIy;
        sRed[wid][2] = minIx; sRed[wid][3] = maxIx;
    }
    __syncthreads();
#pragma unroll
    for (int w = 0; w < 8; ++w) {
        minIy = min(minIy, sRed[w][0]); maxIy = max(maxIy, sRed[w][1]);
        minIx = min(minIx, sRed[w][2]); maxIx = max(maxIx, sRed[w][3]);
    }

    const int r0 = minIy - 1, r1 = maxIy + 2;
    const int c0 = minIx - 1, c1 = maxIx + 2;
    const int nr = r1 - r0 + 1;
    const int nc = c1 - c0 + 1;
    const bool staged = (nr <= SMR) && (nc <= SMC);

    // Phase 2: stage footprint as packed half4 (conflict-free LDS.64 gathers)
    if (staged) {
        const bool interior = (r0 >= 0) && (r1 < HH) && (c0 >= 0) && (c1 < WW);
        if (interior) {
            const float* src0 = img + (size_t)r0 * W3 + (size_t)c0 * 3;
            for (int r = wid; r < nr; r += 8) {
                const float* s = src0 + (size_t)r * W3;
                uint2* dsts = sTile + r * SMC;
                for (int c = lane; c < nc; c += 32) {
                    const float* p = s + c * 3;
                    dsts[c] = pack_texel(p[0], p[1], p[2]);
                }
            }
        } else {
            for (int r = wid; r < nr; r += 8) {
                int rr = min(max(r0 + r, 0), HH - 1);
                const float* s = img + (size_t)rr * W3;
                uint2* dsts = sTile + r * SMC;
                for (int c = lane; c < nc; c += 32) {
                    int cc = min(max(c0 + c, 0), WW - 1);
                    const float* p = s + cc * 3;
                    dsts[c] = pack_texel(p[0], p[1], p[2]);
                }
            }
        }
    }
    __syncthreads();

    // Phase 3: 4x4 cubic gather per output pixel (coords from cache)
#pragma unroll
    for (int k = 0; k < 4; ++k) {
        const int py = py0 + 8 * k;
        const float yy = yyv[k], xx = xxv[k];
        const int iy = __float2int_rd(yy), ix = __float2int_rd(xx);
        const float fy = yy - (float)iy;
        const float fx = xx - (float)ix;

        const float wy[4] = { cub_out(fy + 1.0f), cub_in(fy),
                              cub_in(1.0f - fy), cub_out(2.0f - fy) };
        const float wx0 = cub_out(fx + 1.0f);
        const float wx1 = cub_in(fx);
        const float wx2 = cub_in(1.0f - fx);
        const float wx3 = cub_out(2.0f - fx);

        float a0 = 0.0f, a1 = 0.0f, a2 = 0.0f;
        if (staged) {
            const uint2* p = sTile + (iy - 1 - r0) * SMC + (ix - 1 - c0);
#pragma unroll
            for (int a = 0; a < 4; ++a) {
                uint2 u0 = p[0], u1 = p[1], u2 = p[2], u3 = p[3];
                p += SMC;
                float r0f, g0f, b0f, r1f, g1f, b1f, r2f, g2f, b2f, r3f, g3f, b3f;
                unpack_texel(u0, r0f, g0f, b0f);
                unpack_texel(u1, r1f, g1f, b1f);
                unpack_texel(u2, r2f, g2f, b2f);
                unpack_texel(u3, r3f, g3f, b3f);
                float rc0 = fmaf(wx0, r0f, fmaf(wx1, r1f, fmaf(wx2, r2f, wx3 * r3f)));
                float rc1 = fmaf(wx0, g0f, fmaf(wx1, g1f, fmaf(wx2, g2f, wx3 * g3f)));
                float rc2 = fmaf(wx0, b0f, fmaf(wx1, b1f, fmaf(wx2, b2f, wx3 * b3f)));
                a0 = fmaf(wy[a], rc0, a0);
                a1 = fmaf(wy[a], rc1, a1);
                a2 = fmaf(wy[a], rc2, a2);
            }
        } else {
            // clamped global-gather fallback (footprint exceeded smem budget)
            const float wxa[4] = {wx0, wx1, wx2, wx3};
#pragma unroll
            for (int a = 0; a < 4; ++a) {
                int ty = min(max(iy - 1 + a, 0), HH - 1);
                const float* rowp = img + (size_t)ty * W3;
                float rc0 = 0.0f, rc1 = 0.0f, rc2 = 0.0f;
#pragma unroll
                for (int b = 0; b < 4; ++b) {
                    int txc = min(max(ix - 1 + b, 0), WW - 1);
                    const float* p = rowp + txc * 3;
                    rc0 = fmaf(wxa[b], p[0], rc0);
                    rc1 = fmaf(wxa[b], p[1], rc1);
                    rc2 = fmaf(wxa[b], p[2], rc2);
                }
                a0 = fmaf(wy[a], rc0, a0);
                a1 = fmaf(wy[a], rc1, a1);
                a2 = fmaf(wy[a], rc2, a2);
            }
        }

        float* o = out + ((size_t)py * WW + px) * 3;
        o[0] = a0; o[1] = a1; o[2] = a2;
    }
}

extern "C" void kernel_launch(void* const* d_in, const int* in_sizes, int n_in,
                              void* d_out, int out_size) {
    const float* img  = (const float*)d_in[0];   // (2048, 4096, 3) f32
    const float* disp = (const float*)d_in[1];   // (2, 3, 3) f32
    float* out = (float*)d_out;                  // (2048, 4096, 3) f32

    dim3 grid(WW / TILE, HH / TILE);
    elastic_warp_kernel<<<grid, 256>>>(img, disp, out);
}

// round 8
// speedup vs baseline: 1.9749x; 1.0389x over previous
#include <cuda_runtime.h>
#include <cuda_fp16.h>
#include <cstdint>

// Elastic warp, R8: R7 + HFMA2 x-interpolation on packed half2 texels.
// Removes the 12 per-tap-row F2F converts that made R7 issue-bound (57%):
// per tap row now 8 HFMA2 + 3 cvt (row results only) + 3 FFMA (y-accum, fp32).
// Texel storage (half4 RG|B0, 8B, LDS.64) and fp32 y-accumulation unchanged.

#define HH 2048
#define WW 4096
#define W3 (WW * 3)

constexpr int TILE = 32;
constexpr int SMR  = 44;          // staged rows budget
constexpr int SMC  = 44;          // staged cols budget (half4 each)

__device__ __forceinline__ float cub_in(float t) {
    // (a+2)t^3 - (a+3)t^2 + 1, a = -0.5
    return ((1.5f * t - 2.5f) * t) * t + 1.0f;
}
__device__ __forceinline__ float cub_out(float t) {
    // a t^3 - 5a t^2 + 8a t - 4a, a = -0.5
    return ((-0.5f * t + 2.5f) * t - 4.0f) * t + 2.0f;
}

// Row of the (n_out x 3) spline-upsample matrix for coordinate u in [0,2].
__device__ __forceinline__ void spline_row(float u, float& b0, float& b1, float& b2) {
    int   i0 = __float2int_rd(u);
    float f  = u - (float)i0;
    float w0 = cub_out(f + 1.0f);
    float w1 = cub_in(f);
    float w2 = cub_in(1.0f - f);
    float w3 = cub_out(2.0f - f);
    if (i0 <= 0) {            // taps -1,0,1,2 -> clip 0,0,1,2
        b0 = w0 + w1; b1 = w2; b2 = w3;
    } else if (i0 == 1) {     // taps 0,1,2,3 -> 0,1,2,2
        b0 = w0; b1 = w1; b2 = w2 + w3;
    } else {                  // taps 1,2,3,4 -> 1,2,2,2
        b0 = 0.0f; b1 = w0; b2 = w1 + w2 + w3;
    }
}

__device__ __forceinline__ uint2 pack_texel(float r, float g, float b) {
    __half2 rg = __floats2half2_rn(r, g);
    __half2 bz = __floats2half2_rn(b, 0.0f);
    uint2 v;
    v.x = *reinterpret_cast<uint32_t*>(&rg);
    v.y = *reinterpret_cast<uint32_t*>(&bz);
    return v;
}

__device__ __forceinline__ __half2 as_h2(uint32_t u) {
    return *reinterpret_cast<__half2*>(&u);
}

__global__ void __launch_bounds__(256, 3)
elastic_warp_kernel(const float* __restrict__ img,
                    const float* __restrict__ disp,
                    float* __restrict__ out)
{
    __shared__ uint2 sTile[SMR * SMC];     // half4 texels, 15.5 KB
    __shared__ int   sRed[8][4];

    const int tid  = threadIdx.x;
    const int lane = tid & 31;
    const int wid  = tid >> 5;

    const int px  = blockIdx.x * TILE + lane;   // column (fixed per thread)
    const int py0 = blockIdx.y * TILE + wid;    // rows py0 + 8k, k=0..3

    // Bx row for this column
    float bx0, bx1, bx2;
    spline_row((float)px * (2.0f / (WW - 1)), bx0, bx1, bx2);

    // g[d][y] = sum_x 5*D[d,y,x]*Bx[x]; disp read as uniform broadcast loads
    float g[2][3];
#pragma unroll
    for (int d = 0; d < 2; ++d)
#pragma unroll
        for (int y = 0; y < 3; ++y) {
            const float* dp = disp + d * 9 + y * 3;
            g[d][y] = 5.0f * (dp[0] * bx0 + dp[1] * bx1 + dp[2] * bx2);
        }

    // Phase 1: coords (cached) + exact footprint via block min/max of tap bases
    float yyv[4], xxv[4];
    int minIy =  0x7fffffff, maxIy = -0x7fffffff;
    int minIx =  0x7fffffff, maxIx = -0x7fffffff;
#pragma unroll
    for (int k = 0; k < 4; ++k) {
        int py = py0 + 8 * k;
        float by0, by1, by2;
        spline_row((float)py * (2.0f / (HH - 1)), by0, by1, by2);
        float yy = (float)py + by0 * g[0][0] + by1 * g[0][1] + by2 * g[0][2];
        float xx = (float)px + by0 * g[1][0] + by1 * g[1][1] + by2 * g[1][2];
        yyv[k] = yy; xxv[k] = xx;
        int iy = __float2int_rd(yy), ix = __float2int_rd(xx);
        minIy = min(minIy, iy); maxIy = max(maxIy, iy);
        minIx = min(minIx, ix); maxIx = max(maxIx, ix);
    }
#pragma unroll
    for (int o = 16; o > 0; o >>= 1) {
        minIy = min(minIy, __shfl_xor_sync(0xffffffffu, minIy, o));
        maxIy = max(maxIy, __shfl_xor_sync(0xffffffffu, maxIy, o));
        minIx = min(minIx, __shfl_xor_sync(0xffffffffu, minIx, o));
        maxIx = max(maxIx, __shfl_xor_sync(0xffffffffu, maxIx, o));
    }
    if (lane == 0) {
        sRed[wid][0] = minIy; sRed[wid][1] = maxIy;
        sRed[wid][2] = minIx; sRed[wid][3] = maxIx;
    }
    __syncthreads();
#pragma unroll
    for (int w = 0; w < 8; ++w) {
        minIy = min(minIy, sRed[w][0]); maxIy = max(maxIy, sRed[w][1]);
        minIx = min(minIx, sRed[w][2]); maxIx = max(maxIx, sRed[w][3]);
    }

    const int r0 = minIy - 1, r1 = maxIy + 2;
    const int c0 = minIx - 1, c1 = maxIx + 2;
    const int nr = r1 - r0 + 1;
    const int nc = c1 - c0 + 1;
    const bool staged = (nr <= SMR) && (nc <= SMC);

    // Phase 2: stage footprint as packed half4 (conflict-free LDS.64 gathers)
    if (staged) {
        const bool interior = (r0 >= 0) && (r1 < HH) && (c0 >= 0) && (c1 < WW);
        if (interior) {
            const float* src0 = img + (size_t)r0 * W3 + (size_t)c0 * 3;
            for (int r = wid; r < nr; r += 8) {
                const float* s = src0 + (size_t)r * W3;
                uint2* dsts = sTile + r * SMC;
                for (int c = lane; c < nc; c += 32) {
                    const float* p = s + c * 3;
                    dsts[c] = pack_texel(p[0], p[1], p[2]);
                }
            }
        } else {
            for (int r = wid; r < nr; r += 8) {
                int rr = min(max(r0 + r, 0), HH - 1);
                const float* s = img + (size_t)rr * W3;
                uint2* dsts = sTile + r * SMC;
                for (int c = lane; c < nc; c += 32) {
                    int cc = min(max(c0 + c, 0), WW - 1);
                    const float* p = s + cc * 3;
                    dsts[c] = pack_texel(p[0], p[1], p[2]);
                }
            }
        }
    }
    __syncthreads();

    // Phase 3: 4x4 cubic gather per output pixel (coords from cache)
#pragma unroll
    for (int k = 0; k < 4; ++k) {
        const int py = py0 + 8 * k;
        const float yy = yyv[k], xx = xxv[k];
        const int iy = __float2int_rd(yy), ix = __float2int_rd(xx);
        const float fy = yy - (float)iy;
        const float fx = xx - (float)ix;

        const float wy[4] = { cub_out(fy + 1.0f), cub_in(fy),
                              cub_in(1.0f - fy), cub_out(2.0f - fy) };
        const float wx0 = cub_out(fx + 1.0f);
        const float wx1 = cub_in(fx);
        const float wx2 = cub_in(1.0f - fx);
        const float wx3 = cub_out(2.0f - fx);

        float a0 = 0.0f, a1 = 0.0f, a2 = 0.0f;
        if (staged) {
            const __half2 wxh0 = __float2half2_rn(wx0);
            const __half2 wxh1 = __float2half2_rn(wx1);
            const __half2 wxh2 = __float2half2_rn(wx2);
            const __half2 wxh3 = __float2half2_rn(wx3);
            const uint2* p = sTile + (iy - 1 - r0) * SMC + (ix - 1 - c0);
#pragma unroll
            for (int a = 0; a < 4; ++a) {
                uint2 u0 = p[0], u1 = p[1], u2 = p[2], u3 = p[3];
                p += SMC;
                // x-interp in packed fp16: rg lanes together, b in low lane
                __half2 rg = __hmul2(wxh0, as_h2(u0.x));
                rg = __hfma2(wxh1, as_h2(u1.x), rg);
                rg = __hfma2(wxh2, as_h2(u2.x), rg);
                rg = __hfma2(wxh3, as_h2(u3.x), rg);
                __half2 bb = __hmul2(wxh0, as_h2(u0.y));
                bb = __hfma2(wxh1, as_h2(u1.y), bb);
                bb = __hfma2(wxh2, as_h2(u2.y), bb);
                bb = __hfma2(wxh3, as_h2(u3.y), bb);
                float2 frg = __half22float2(rg);
                a0 = fmaf(wy[a], frg.x, a0);
                a1 = fmaf(wy[a], frg.y, a1);
                a2 = fmaf(wy[a], __low2float(bb), a2);
            }
        } else {
            // clamped global-gather fallback (footprint exceeded smem budget)
            const float wxa[4] = {wx0, wx1, wx2, wx3};
#pragma unroll
            for (int a = 0; a < 4; ++a) {
                int ty = min(max(iy - 1 + a, 0), HH - 1);
                const float* rowp = img + (size_t)ty * W3;
                float rc0 = 0.0f, rc1 = 0.0f, rc2 = 0.0f;
#pragma unroll
                for (int b = 0; b < 4; ++b) {
                    int txc = min(max(ix - 1 + b, 0), WW - 1);
                    const float* p = rowp + txc * 3;
                    rc0 = fmaf(wxa[b], p[0], rc0);
                    rc1 = fmaf(wxa[b], p[1], rc1);
                    rc2 = fmaf(wxa[b], p[2], rc2);
                }
                a0 = fmaf(wy[a], rc0, a0);
                a1 = fmaf(wy[a], rc1, a1);
                a2 = fmaf(wy[a], rc2, a2);
            }
        }

        float* o = out + ((size_t)py * WW + px) * 3;
        o[0] = a0; o[1] = a1; o[2] = a2;
    }
}

extern "C" void kernel_launch(void* const* d_in, const int* in_sizes, int n_in,
                              void* d_out, int out_size) {
    const float* img  = (const float*)d_in[0];   // (2048, 4096, 3) f32
    const float* disp = (const float*)d_in[1];   // (2, 3, 3) f32
    float* out = (float*)d_out;                  // (2048, 4096, 3) f32

    dim3 grid(WW / TILE, HH / TILE);
    elastic_warp_kernel<<<grid, 256>>>(img, disp, out);
}